// round 6
// baseline (speedup 1.0000x reference)
#include <cuda_runtime.h>
#include <cstdint>

#define NB   64
#define NT   512
#define NIN  256
#define NH   512
#define NOUT 256

// ---- static device scratch (no runtime allocation) --------------------------
__device__ float  g_xp[NB * NT * NH];
__device__ float  g_out0[NB * NT * NH];
__device__ float  g_hfin[NB][NH];        // final hidden, scalar layout for proj

// ---- recurrence config ------------------------------------------------------
#define G_J 8                 // CTAs per cluster (j-slices)
#define NCTA 128              // 16 clusters x 8
#define CTA_J 64
#define RTHREADS 256          // 8 warps; warp = 8-j group, lane = k subset

// ---- f32x2 packed helpers ---------------------------------------------------
typedef unsigned long long u64t;
__device__ __forceinline__ u64t bcast2(float w) {
    u64t d; unsigned u = __float_as_uint(w);
    asm("mov.b64 %0, {%1, %1};" : "=l"(d) : "r"(u));
    return d;
}
__device__ __forceinline__ u64t fmax2(u64t a, u64t b, u64t c) {
    u64t d; asm("fma.rn.f32x2 %0, %1, %2, %3;" : "=l"(d) : "l"(a), "l"(b), "l"(c));
    return d;
}
__device__ __forceinline__ u64t addx2(u64t a, u64t b) {
    u64t d; asm("add.rn.f32x2 %0, %1, %2;" : "=l"(d) : "l"(a), "l"(b));
    return d;
}
__device__ __forceinline__ float2 unpk2(u64t v) {
    unsigned lo, hi; asm("mov.b64 {%0, %1}, %2;" : "=r"(lo), "=r"(hi) : "l"(v));
    return make_float2(__uint_as_float(lo), __uint_as_float(hi));
}
__device__ __forceinline__ u64t pk2(float x, float y) {
    u64t d; asm("mov.b64 %0, {%1, %2};" : "=l"(d) : "r"(__float_as_uint(x)), "r"(__float_as_uint(y)));
    return d;
}

// ---- DSMEM / mbarrier helpers -----------------------------------------------
__device__ __forceinline__ uint32_t smem_u32(const void* p) {
    return (uint32_t)__cvta_generic_to_shared(p);
}
__device__ __forceinline__ void st_cluster_b64(uint32_t local_addr, int rank, u64t v) {
    uint32_t ra;
    asm volatile("mapa.shared::cluster.u32 %0, %1, %2;" : "=r"(ra) : "r"(local_addr), "r"(rank));
    asm volatile("st.shared::cluster.b64 [%0], %1;" :: "r"(ra), "l"(v) : "memory");
}
__device__ __forceinline__ void mbar_init(uint32_t mbar, unsigned count) {
    asm volatile("mbarrier.init.shared.b64 [%0], %1;" :: "r"(mbar), "r"(count) : "memory");
}
__device__ __forceinline__ void mbar_arrive_rank(uint32_t mbar, int rank) {
    asm volatile("{\n\t.reg .b32 ra;\n\t"
                 "mapa.shared::cluster.u32 ra, %0, %1;\n\t"
                 "mbarrier.arrive.release.cluster.shared::cluster.b64 _, [ra];\n\t}"
                 :: "r"(mbar), "r"(rank) : "memory");
}
__device__ __forceinline__ void mbar_wait_cluster(uint32_t mbar, unsigned parity) {
    unsigned done = 0;
    while (!done) {
        asm volatile("{\n\t.reg .pred p;\n\t"
                     "mbarrier.try_wait.parity.acquire.cluster.shared::cta.b64 p, [%1], %2, 0x989680;\n\t"
                     "selp.b32 %0, 1, 0, p;\n\t}"
                     : "=r"(done) : "r"(mbar), "r"(parity) : "memory");
    }
}
__device__ __forceinline__ void fence_cluster() {
    asm volatile("fence.acq_rel.cluster;" ::: "memory");
}
__device__ __forceinline__ void cluster_sync_hw() {
    asm volatile("barrier.cluster.arrive.aligned;" ::: "memory");
    asm volatile("barrier.cluster.wait.aligned;"   ::: "memory");
}

// h_new[b][j] = tanh( xp[b][t][j] + sum_k h[b][k]*Whh[j][k] )
// Cluster (8 CTAs) = one batch group of 4 batches; CTA rank gj owns j-slice
// [gj*64,+64). Full h (4 batches x 512 j, per-batch scalar rows) lives in each
// CTA's SMEM; new values are scattered to all 8 cluster CTAs via DSMEM, synced
// with a per-step mbarrier (2 alternating barriers, count=8).
__global__ void __launch_bounds__(RTHREADS, 1) __cluster_dims__(G_J, 1, 1)
rnn_kernel(const float* __restrict__ xp, const float* __restrict__ Whh,
           float* __restrict__ outseq, int store_out)
{
    __shared__ __align__(16) float s_h[2][4][NH];   // [buf][batch][j]  16 KB
    __shared__ __align__(8)  unsigned long long s_mbar[2];

    const int tid    = threadIdx.x;
    const int w      = tid >> 5;
    const int lane   = tid & 31;
    const int gb     = blockIdx.x >> 3;          // batch group / cluster id
    const int gj     = blockIdx.x & 7;           // rank within cluster
    const int b_base = gb * 4;
    const int j_base = gj * CTA_J;

    // ---- W pre-packed as j-pairs in registers ---------------------------------
    // wpk[kk][jp][s] = ( Whh[j0][k0+s], Whh[j0+1][k0+s] ), j0 = j_base+w*8+jp*2,
    // k0 = 2*lane + 64*kk
    u64t wpk[8][4][2];
    #pragma unroll
    for (int kk = 0; kk < 8; kk++) {
        const int k0 = 2 * lane + 64 * kk;
        #pragma unroll
        for (int jp = 0; jp < 4; jp++) {
            const int j0 = j_base + w * 8 + jp * 2;
            wpk[kk][jp][0] = pk2(__ldg(Whh + j0 * NH + k0),
                                 __ldg(Whh + (j0 + 1) * NH + k0));
            wpk[kk][jp][1] = pk2(__ldg(Whh + j0 * NH + k0 + 1),
                                 __ldg(Whh + (j0 + 1) * NH + k0 + 1));
        }
    }

    // init: barriers + zero h buffer 0
    if (tid == 0) {
        mbar_init(smem_u32(&s_mbar[0]), G_J);
        mbar_init(smem_u32(&s_mbar[1]), G_J);
    }
    for (int idx = tid; idx < 4 * NH; idx += RTHREADS)
        ((float*)s_h[0])[idx] = 0.f;
    __syncthreads();
    cluster_sync_hw();                 // peers' smem + barriers valid

    const uint32_t mb[2] = { smem_u32(&s_mbar[0]), smem_u32(&s_mbar[1]) };

    // ---- final output mapping after reduce-scatter ---------------------------
    const int bsel  = 2 * ((lane >> 4) & 1) + ((lane >> 3) & 1);
    const int jpsel = 2 * ((lane >> 2) & 1) + ((lane >> 1) & 1);
    const int bglob = b_base + bsel;
    const int j0    = j_base + w * 8 + jpsel * 2;
    const uint32_t dst_addr[2] = { smem_u32(&s_h[0][bsel][j0]),
                                   smem_u32(&s_h[1][bsel][j0]) };
    const int r0 = (lane & 1) * 4;      // duplicate-lane parity splits 8 ranks

    #pragma unroll 1
    for (int t = 0; t < NT; ++t) {
        const int cur = t & 1, nxt = cur ^ 1;

        // xp prefetch for this thread's (b, j0..j0+1) — before the wait
        const int row = (bglob * NT + t) * NH + j0;
        const float2 xv = __ldg((const float2*)(xp + row));

        // wait for exchange t-1 (none at t=0)
        if (t > 0) {
            const int e = t - 1;
            mbar_wait_cluster(mb[e & 1], (unsigned)((e >> 1) & 1));
        }

        // ---- packed-FMA partials: acc[b*4+jp] = (pre_j0, pre_j1) for batch b
        u64t acc[16];
        #pragma unroll
        for (int m = 0; m < 16; m++) acc[m] = 0ull;

        #pragma unroll
        for (int kk = 0; kk < 8; kk++) {
            const int k0 = 2 * lane + 64 * kk;
            const float2 hb0 = *(const float2*)&s_h[cur][0][k0];
            const float2 hb1 = *(const float2*)&s_h[cur][1][k0];
            const float2 hb2 = *(const float2*)&s_h[cur][2][k0];
            const float2 hb3 = *(const float2*)&s_h[cur][3][k0];
            const u64t d0l = bcast2(hb0.x), d0h = bcast2(hb0.y);
            const u64t d1l = bcast2(hb1.x), d1h = bcast2(hb1.y);
            const u64t d2l = bcast2(hb2.x), d2h = bcast2(hb2.y);
            const u64t d3l = bcast2(hb3.x), d3h = bcast2(hb3.y);
            #pragma unroll
            for (int jp = 0; jp < 4; jp++) {
                const u64t wl = wpk[kk][jp][0], wh = wpk[kk][jp][1];
                acc[0*4+jp] = fmax2(wl, d0l, acc[0*4+jp]);
                acc[0*4+jp] = fmax2(wh, d0h, acc[0*4+jp]);
                acc[1*4+jp] = fmax2(wl, d1l, acc[1*4+jp]);
                acc[1*4+jp] = fmax2(wh, d1h, acc[1*4+jp]);
                acc[2*4+jp] = fmax2(wl, d2l, acc[2*4+jp]);
                acc[2*4+jp] = fmax2(wh, d2h, acc[2*4+jp]);
                acc[3*4+jp] = fmax2(wl, d3l, acc[3*4+jp]);
                acc[3*4+jp] = fmax2(wh, d3h, acc[3*4+jp]);
            }
        }

        // ---- in-warp reduce-scatter (k-split across lanes) -------------------
        u64t v8[8];
        #pragma unroll
        for (int m = 0; m < 8; m++) {
            const u64t send = (lane & 16) ? acc[m] : acc[m + 8];
            const u64t kept = (lane & 16) ? acc[m + 8] : acc[m];
            v8[m] = addx2(kept, __shfl_xor_sync(0xffffffffu, send, 16));
        }
        u64t v4[4];
        #pragma unroll
        for (int m = 0; m < 4; m++) {
            const u64t send = (lane & 8) ? v8[m] : v8[m + 4];
            const u64t kept = (lane & 8) ? v8[m + 4] : v8[m];
            v4[m] = addx2(kept, __shfl_xor_sync(0xffffffffu, send, 8));
        }
        u64t v2[2];
        #pragma unroll
        for (int m = 0; m < 2; m++) {
            const u64t send = (lane & 4) ? v4[m] : v4[m + 2];
            const u64t kept = (lane & 4) ? v4[m + 2] : v4[m];
            v2[m] = addx2(kept, __shfl_xor_sync(0xffffffffu, send, 4));
        }
        u64t v1;
        {
            const u64t send = (lane & 2) ? v2[0] : v2[1];
            const u64t kept = (lane & 2) ? v2[1] : v2[0];
            v1 = addx2(kept, __shfl_xor_sync(0xffffffffu, send, 2));
        }
        v1 = addx2(v1, __shfl_xor_sync(0xffffffffu, v1, 1)); // lanes l,l^1 duplicate

        // ---- activation + outputs -------------------------------------------
        const float2 s  = unpk2(v1);
        const float  h0 = tanhf(s.x + xv.x);     // j0
        const float  h1 = tanhf(s.y + xv.y);     // j0+1
        const u64t   hv = pk2(h0, h1);

        if (t < NT - 1) {
            const uint32_t da = dst_addr[nxt];
            #pragma unroll
            for (int r = 0; r < 4; r++)
                st_cluster_b64(da, r0 + r, hv);
        }
        if (lane & 1) {
            if (store_out) *(float2*)(outseq + row) = make_float2(h0, h1);
            if (t == NT - 1) *(float2*)(&g_hfin[bglob][j0]) = make_float2(h0, h1);
        }

        if (t < NT - 1) {
            __syncthreads();                       // all threads' scatters issued
            if (tid == 0) {
                fence_cluster();                   // order stores at cluster scope
                const uint32_t m = mb[t & 1];
                #pragma unroll
                for (int r = 0; r < G_J; r++)
                    mbar_arrive_rank(m, r);
            }
        }
    }
}

// ---- big tiled fp32 GEMM: C[M,N] = A[M,K] @ B[N,K]^T + bias1 (+bias2) -------
#define GBM 128
#define GBN 64
#define GBK 16

__global__ void __launch_bounds__(256)
gemm128_nt_bias(const float* __restrict__ A, const float* __restrict__ B,
                const float* __restrict__ bias1, const float* __restrict__ bias2,
                float* __restrict__ C, int M, int N, int K)
{
    __shared__ __align__(16) float As[GBK][GBM];
    __shared__ __align__(16) float Bs[GBK][GBN];

    const int tid = threadIdx.x;
    const int m0 = blockIdx.x * GBM;
    const int n0 = blockIdx.y * GBN;
    const int tx = tid & 15;
    const int ty = tid >> 4;
    const int lrA = tid >> 1, lcA = tid & 1;
    const int lrB = tid >> 2, lcB = tid & 3;

    float acc[8][4];
    #pragma unroll
    for (int i = 0; i < 8; i++)
        #pragma unroll
        for (int j = 0; j < 4; j++) acc[i][j] = 0.f;

    for (int kk0 = 0; kk0 < K; kk0 += GBK) {
        const float4 av0 = *(const float4*)(A + (m0 + lrA) * K + kk0 + lcA * 8);
        const float4 av1 = *(const float4*)(A + (m0 + lrA) * K + kk0 + lcA * 8 + 4);
        const float4 bv  = *(const float4*)(B + (n0 + lrB) * K + kk0 + lcB * 4);
        __syncthreads();
        As[lcA*8+0][lrA] = av0.x; As[lcA*8+1][lrA] = av0.y;
        As[lcA*8+2][lrA] = av0.z; As[lcA*8+3][lrA] = av0.w;
        As[lcA*8+4][lrA] = av1.x; As[lcA*8+5][lrA] = av1.y;
        As[lcA*8+6][lrA] = av1.z; As[lcA*8+7][lrA] = av1.w;
        Bs[lcB*4+0][lrB] = bv.x;  Bs[lcB*4+1][lrB] = bv.y;
        Bs[lcB*4+2][lrB] = bv.z;  Bs[lcB*4+3][lrB] = bv.w;
        __syncthreads();

        #pragma unroll
        for (int k = 0; k < GBK; ++k) {
            const float4 a0 = *(const float4*)(&As[k][ty * 8]);
            const float4 a1 = *(const float4*)(&As[k][ty * 8 + 4]);
            const float4 b  = *(const float4*)(&Bs[k][tx * 4]);
            const float avv[8] = {a0.x, a0.y, a0.z, a0.w, a1.x, a1.y, a1.z, a1.w};
            const float bvv[4] = {b.x, b.y, b.z, b.w};
            #pragma unroll
            for (int i = 0; i < 8; i++)
                #pragma unroll
                for (int j = 0; j < 4; j++)
                    acc[i][j] += avv[i] * bvv[j];
        }
    }

    float bsv[4];
    #pragma unroll
    for (int j = 0; j < 4; j++) {
        bsv[j] = bias1 ? bias1[n0 + tx * 4 + j] : 0.f;
        if (bias2) bsv[j] += bias2[n0 + tx * 4 + j];
    }
    #pragma unroll
    for (int i = 0; i < 8; i++) {
        const int m = m0 + ty * 8 + i;
        float4 o;
        o.x = acc[i][0] + bsv[0];
        o.y = acc[i][1] + bsv[1];
        o.z = acc[i][2] + bsv[2];
        o.w = acc[i][3] + bsv[3];
        *(float4*)(C + m * N + n0 + tx * 4) = o;
    }
}

// ---- small GEMM (64x64 tile) for the final projection (M=64) ----------------
#define BM 64
#define BN 64
#define BK 16

__global__ void __launch_bounds__(256)
gemm_nt_bias(const float* __restrict__ A, const float* __restrict__ B,
             const float* __restrict__ bias1, const float* __restrict__ bias2,
             float* __restrict__ C, int M, int N, int K)
{
    __shared__ __align__(16) float As[BK][BM];
    __shared__ __align__(16) float Bs[BK][BN];

    const int tid = threadIdx.x;
    const int m0 = blockIdx.x * BM;
    const int n0 = blockIdx.y * BN;
    const int tx = tid & 15;
    const int ty = tid >> 4;
    const int lr = tid >> 2;
    const int lc = tid & 3;

    float acc[4][4];
    #pragma unroll
    for (int i = 0; i < 4; i++)
        #pragma unroll
        for (int j = 0; j < 4; j++) acc[i][j] = 0.f;

    for (int kk0 = 0; kk0 < K; kk0 += BK) {
        const float4 av = *(const float4*)(A + (m0 + lr) * K + kk0 + lc * 4);
        const float4 bv = *(const float4*)(B + (n0 + lr) * K + kk0 + lc * 4);
        __syncthreads();
        As[lc*4+0][lr] = av.x; As[lc*4+1][lr] = av.y;
        As[lc*4+2][lr] = av.z; As[lc*4+3][lr] = av.w;
        Bs[lc*4+0][lr] = bv.x; Bs[lc*4+1][lr] = bv.y;
        Bs[lc*4+2][lr] = bv.z; Bs[lc*4+3][lr] = bv.w;
        __syncthreads();

        #pragma unroll
        for (int k = 0; k < BK; ++k) {
            const float4 a = *(const float4*)(&As[k][ty * 4]);
            const float4 b = *(const float4*)(&Bs[k][tx * 4]);
            const float avv[4] = {a.x, a.y, a.z, a.w};
            const float bvv[4] = {b.x, b.y, b.z, b.w};
            #pragma unroll
            for (int i = 0; i < 4; i++)
                #pragma unroll
                for (int j = 0; j < 4; j++)
                    acc[i][j] += avv[i] * bvv[j];
        }
    }

    #pragma unroll
    for (int i = 0; i < 4; i++) {
        const int m = m0 + ty * 4 + i;
        const int n = n0 + tx * 4;
        float bsv[4];
        #pragma unroll
        for (int j = 0; j < 4; j++) {
            bsv[j] = bias1 ? bias1[n + j] : 0.f;
            if (bias2) bsv[j] += bias2[n + j];
        }
        float4 o;
        o.x = acc[i][0] + bsv[0];
        o.y = acc[i][1] + bsv[1];
        o.z = acc[i][2] + bsv[2];
        o.w = acc[i][3] + bsv[3];
        *(float4*)(C + m * N + n) = o;
    }
}

// ---- launch -----------------------------------------------------------------
extern "C" void kernel_launch(void* const* d_in, const int* in_sizes, int n_in,
                              void* d_out, int out_size)
{
    const float* x     = (const float*)d_in[0];
    const float* W_ih0 = (const float*)d_in[1];
    const float* W_hh0 = (const float*)d_in[2];
    const float* b_ih0 = (const float*)d_in[3];
    const float* b_hh0 = (const float*)d_in[4];
    const float* W_ih1 = (const float*)d_in[5];
    const float* W_hh1 = (const float*)d_in[6];
    const float* b_ih1 = (const float*)d_in[7];
    const float* b_hh1 = (const float*)d_in[8];
    const float* W_out = (const float*)d_in[9];
    const float* b_out = (const float*)d_in[10];
    float* out = (float*)d_out;

    float *xp, *out0, *hfin;
    cudaGetSymbolAddress((void**)&xp,   g_xp);
    cudaGetSymbolAddress((void**)&out0, g_out0);
    cudaGetSymbolAddress((void**)&hfin, g_hfin);

    const int M = NB * NT;  // 32768

    // xp0 = x @ W_ih0^T + b_ih0 + b_hh0
    {
        dim3 grid(M / GBM, NH / GBN);
        gemm128_nt_bias<<<grid, 256>>>(x, W_ih0, b_ih0, b_hh0, xp, M, NH, NIN);
    }
    // layer 0 recurrence (stores full sequence)
    rnn_kernel<<<NCTA, RTHREADS>>>(xp, W_hh0, out0, 1);

    // xp1 = out0 @ W_ih1^T + b_ih1 + b_hh1
    {
        dim3 grid(M / GBM, NH / GBN);
        gemm128_nt_bias<<<grid, 256>>>(out0, W_ih1, b_ih1, b_hh1, xp, M, NH, NH);
    }
    // layer 1 recurrence (final hidden -> g_hfin)
    rnn_kernel<<<NCTA, RTHREADS>>>(xp, W_hh1, nullptr, 0);

    // out = h_last @ W_out^T + b_out
    {
        dim3 grid(NB / BM, NOUT / BN);
        gemm_nt_bias<<<grid, 256>>>(hfin, W_out, b_out, nullptr, out, NB, NOUT, NH);
    }
}

// round 7
// speedup vs baseline: 1.7164x; 1.7164x over previous
#include <cuda_runtime.h>
#include <cstdint>

#define NB   64
#define NT   512
#define NIN  256
#define NH   512
#define NOUT 256

// ---- static device scratch (no runtime allocation) --------------------------
__device__ float  g_xp[NB * NT * NH];
__device__ float  g_out0[NB * NT * NH];
__device__ float  g_hfin[NB][NH];        // final hidden, scalar layout for proj

// ---- recurrence config ------------------------------------------------------
#define G_J 8                 // CTAs per cluster (j-slices)
#define NCTA 128              // 16 clusters x 8
#define CTA_J 64
#define RTHREADS 256          // 8 warps; warp = 8-j group, lane = k subset

// ---- f32x2 packed helpers ---------------------------------------------------
typedef unsigned long long u64t;
__device__ __forceinline__ u64t bcast2(float w) {
    u64t d; unsigned u = __float_as_uint(w);
    asm("mov.b64 %0, {%1, %1};" : "=l"(d) : "r"(u));
    return d;
}
__device__ __forceinline__ u64t fmax2(u64t a, u64t b, u64t c) {
    u64t d; asm("fma.rn.f32x2 %0, %1, %2, %3;" : "=l"(d) : "l"(a), "l"(b), "l"(c));
    return d;
}
__device__ __forceinline__ u64t addx2(u64t a, u64t b) {
    u64t d; asm("add.rn.f32x2 %0, %1, %2;" : "=l"(d) : "l"(a), "l"(b));
    return d;
}
__device__ __forceinline__ float2 unpk2(u64t v) {
    unsigned lo, hi; asm("mov.b64 {%0, %1}, %2;" : "=r"(lo), "=r"(hi) : "l"(v));
    return make_float2(__uint_as_float(lo), __uint_as_float(hi));
}
__device__ __forceinline__ u64t pk2(float x, float y) {
    u64t d; asm("mov.b64 %0, {%1, %2};" : "=l"(d) : "r"(__float_as_uint(x)), "r"(__float_as_uint(y)));
    return d;
}

// ---- DSMEM helpers ----------------------------------------------------------
__device__ __forceinline__ uint32_t smem_u32(const void* p) {
    return (uint32_t)__cvta_generic_to_shared(p);
}
__device__ __forceinline__ void st_cluster_b64(uint32_t local_addr, int rank, u64t v) {
    uint32_t ra;
    asm volatile("mapa.shared::cluster.u32 %0, %1, %2;" : "=r"(ra) : "r"(local_addr), "r"(rank));
    asm volatile("st.shared::cluster.b64 [%0], %1;" :: "r"(ra), "l"(v) : "memory");
}
// barrier.cluster: arrive has release, wait has acquire semantics (cluster scope)
__device__ __forceinline__ void cluster_arrive_hw() {
    asm volatile("barrier.cluster.arrive.aligned;" ::: "memory");
}
__device__ __forceinline__ void cluster_wait_hw() {
    asm volatile("barrier.cluster.wait.aligned;" ::: "memory");
}

// h_new[b][j] = tanh( xp[b][t][j] + sum_k h[b][k]*Whh[j][k] )
// Cluster (8 CTAs) = one batch group of 4 batches; CTA rank gj owns j-slice
// [gj*64,+64). Full h (4 batches x 512 j) lives in each CTA's SMEM; new values
// are scattered to all 8 cluster CTAs via DSMEM; one split arrive/wait
// barrier.cluster per step (arrive after scatter, wait after next xp prefetch).
__global__ void __launch_bounds__(RTHREADS, 1) __cluster_dims__(G_J, 1, 1)
rnn_kernel(const float* __restrict__ xp, const float* __restrict__ Whh,
           float* __restrict__ outseq, int store_out)
{
    __shared__ __align__(16) float s_h[2][4][NH];   // [buf][batch][j]  16 KB

    const int tid    = threadIdx.x;
    const int w      = tid >> 5;
    const int lane   = tid & 31;
    const int gb     = blockIdx.x >> 3;          // batch group / cluster id
    const int gj     = blockIdx.x & 7;           // rank within cluster
    const int b_base = gb * 4;
    const int j_base = gj * CTA_J;

    // ---- W pre-packed as j-pairs in registers -------------------------------
    // wpk[kk][jp][s] = ( Whh[j0][k0+s], Whh[j0+1][k0+s] ),
    // j0 = j_base + w*8 + jp*2,  k0 = 2*lane + 64*kk
    u64t wpk[8][4][2];
    #pragma unroll
    for (int kk = 0; kk < 8; kk++) {
        const int k0 = 2 * lane + 64 * kk;
        #pragma unroll
        for (int jp = 0; jp < 4; jp++) {
            const int j0 = j_base + w * 8 + jp * 2;
            wpk[kk][jp][0] = pk2(__ldg(Whh + j0 * NH + k0),
                                 __ldg(Whh + (j0 + 1) * NH + k0));
            wpk[kk][jp][1] = pk2(__ldg(Whh + j0 * NH + k0 + 1),
                                 __ldg(Whh + (j0 + 1) * NH + k0 + 1));
        }
    }

    // zero initial h buffer (buf 0), local only
    for (int idx = tid; idx < 4 * NH; idx += RTHREADS)
        ((float*)s_h[0])[idx] = 0.f;
    __syncthreads();

    // ---- final output mapping after reduce-scatter --------------------------
    const int bsel  = 2 * ((lane >> 4) & 1) + ((lane >> 3) & 1);
    const int jpsel = 2 * ((lane >> 2) & 1) + ((lane >> 1) & 1);
    const int bglob = b_base + bsel;
    const int j0    = j_base + w * 8 + jpsel * 2;
    const uint32_t dst_addr[2] = { smem_u32(&s_h[0][bsel][j0]),
                                   smem_u32(&s_h[1][bsel][j0]) };
    const int r0 = (lane & 1) * 4;      // duplicate-lane parity splits 8 ranks

    // peers' SMEM valid + initial zero buffer visible
    cluster_arrive_hw();
    cluster_wait_hw();

    #pragma unroll 1
    for (int t = 0; t < NT; ++t) {
        const int cur = t & 1, nxt = cur ^ 1;

        // xp prefetch (independent of peers) BEFORE the wait for step t-1's
        // exchange -> L2 latency hidden inside the barrier wait window.
        const int row = (bglob * NT + t) * NH + j0;
        const float2 xv = __ldg((const float2*)(xp + row));

        if (t > 0) cluster_wait_hw();    // acquire peers' scatters into buf[cur]

        // ---- packed-FMA partials: acc[b*4+jp] = (pre_j0, pre_j1) ------------
        u64t acc[16];
        #pragma unroll
        for (int m = 0; m < 16; m++) acc[m] = 0ull;

        #pragma unroll
        for (int kk = 0; kk < 8; kk++) {
            const int k0v = 2 * lane + 64 * kk;
            const float2 hb0 = *(const float2*)&s_h[cur][0][k0v];
            const float2 hb1 = *(const float2*)&s_h[cur][1][k0v];
            const float2 hb2 = *(const float2*)&s_h[cur][2][k0v];
            const float2 hb3 = *(const float2*)&s_h[cur][3][k0v];
            const u64t d0l = bcast2(hb0.x), d0h = bcast2(hb0.y);
            const u64t d1l = bcast2(hb1.x), d1h = bcast2(hb1.y);
            const u64t d2l = bcast2(hb2.x), d2h = bcast2(hb2.y);
            const u64t d3l = bcast2(hb3.x), d3h = bcast2(hb3.y);
            #pragma unroll
            for (int jp = 0; jp < 4; jp++) {
                const u64t wl = wpk[kk][jp][0], wh = wpk[kk][jp][1];
                acc[0*4+jp] = fmax2(wl, d0l, acc[0*4+jp]);
                acc[0*4+jp] = fmax2(wh, d0h, acc[0*4+jp]);
                acc[1*4+jp] = fmax2(wl, d1l, acc[1*4+jp]);
                acc[1*4+jp] = fmax2(wh, d1h, acc[1*4+jp]);
                acc[2*4+jp] = fmax2(wl, d2l, acc[2*4+jp]);
                acc[2*4+jp] = fmax2(wh, d2h, acc[2*4+jp]);
                acc[3*4+jp] = fmax2(wl, d3l, acc[3*4+jp]);
                acc[3*4+jp] = fmax2(wh, d3h, acc[3*4+jp]);
            }
        }

        // ---- in-warp reduce-scatter (k-split across lanes) ------------------
        u64t v8[8];
        #pragma unroll
        for (int m = 0; m < 8; m++) {
            const u64t send = (lane & 16) ? acc[m] : acc[m + 8];
            const u64t kept = (lane & 16) ? acc[m + 8] : acc[m];
            v8[m] = addx2(kept, __shfl_xor_sync(0xffffffffu, send, 16));
        }
        u64t v4[4];
        #pragma unroll
        for (int m = 0; m < 4; m++) {
            const u64t send = (lane & 8) ? v8[m] : v8[m + 4];
            const u64t kept = (lane & 8) ? v8[m + 4] : v8[m];
            v4[m] = addx2(kept, __shfl_xor_sync(0xffffffffu, send, 8));
        }
        u64t v2[2];
        #pragma unroll
        for (int m = 0; m < 2; m++) {
            const u64t send = (lane & 4) ? v4[m] : v4[m + 2];
            const u64t kept = (lane & 4) ? v4[m + 2] : v4[m];
            v2[m] = addx2(kept, __shfl_xor_sync(0xffffffffu, send, 4));
        }
        u64t v1;
        {
            const u64t send = (lane & 2) ? v2[0] : v2[1];
            const u64t kept = (lane & 2) ? v2[1] : v2[0];
            v1 = addx2(kept, __shfl_xor_sync(0xffffffffu, send, 2));
        }
        v1 = addx2(v1, __shfl_xor_sync(0xffffffffu, v1, 1)); // lanes l,l^1 duplicate

        // ---- activation + outputs ------------------------------------------
        const float2 s  = unpk2(v1);
        const float  h0 = tanhf(s.x + xv.x);     // j0
        const float  h1 = tanhf(s.y + xv.y);     // j0+1
        const u64t   hv = pk2(h0, h1);

        if (t < NT - 1) {
            // scatter to all 8 cluster CTAs' buf[nxt] (lane parity splits ranks)
            const uint32_t da = dst_addr[nxt];
            #pragma unroll
            for (int r = 0; r < 4; r++)
                st_cluster_b64(da, r0 + r, hv);
            cluster_arrive_hw();          // release the scatters (per-thread)
        }
        // side outputs after arrive: off the critical path
        if (lane & 1) {
            if (store_out) *(float2*)(outseq + row) = make_float2(h0, h1);
            if (t == NT - 1) *(float2*)(&g_hfin[bglob][j0]) = make_float2(h0, h1);
        }
    }
}

// ---- big tiled fp32 GEMM: C[M,N] = A[M,K] @ B[N,K]^T + bias1 (+bias2) -------
#define GBM 128
#define GBN 64
#define GBK 16

__global__ void __launch_bounds__(256)
gemm128_nt_bias(const float* __restrict__ A, const float* __restrict__ B,
                const float* __restrict__ bias1, const float* __restrict__ bias2,
                float* __restrict__ C, int M, int N, int K)
{
    __shared__ __align__(16) float As[GBK][GBM];
    __shared__ __align__(16) float Bs[GBK][GBN];

    const int tid = threadIdx.x;
    const int m0 = blockIdx.x * GBM;
    const int n0 = blockIdx.y * GBN;
    const int tx = tid & 15;
    const int ty = tid >> 4;
    const int lrA = tid >> 1, lcA = tid & 1;
    const int lrB = tid >> 2, lcB = tid & 3;

    float acc[8][4];
    #pragma unroll
    for (int i = 0; i < 8; i++)
        #pragma unroll
        for (int j = 0; j < 4; j++) acc[i][j] = 0.f;

    for (int kk0 = 0; kk0 < K; kk0 += GBK) {
        const float4 av0 = *(const float4*)(A + (m0 + lrA) * K + kk0 + lcA * 8);
        const float4 av1 = *(const float4*)(A + (m0 + lrA) * K + kk0 + lcA * 8 + 4);
        const float4 bv  = *(const float4*)(B + (n0 + lrB) * K + kk0 + lcB * 4);
        __syncthreads();
        As[lcA*8+0][lrA] = av0.x; As[lcA*8+1][lrA] = av0.y;
        As[lcA*8+2][lrA] = av0.z; As[lcA*8+3][lrA] = av0.w;
        As[lcA*8+4][lrA] = av1.x; As[lcA*8+5][lrA] = av1.y;
        As[lcA*8+6][lrA] = av1.z; As[lcA*8+7][lrA] = av1.w;
        Bs[lcB*4+0][lrB] = bv.x;  Bs[lcB*4+1][lrB] = bv.y;
        Bs[lcB*4+2][lrB] = bv.z;  Bs[lcB*4+3][lrB] = bv.w;
        __syncthreads();

        #pragma unroll
        for (int k = 0; k < GBK; ++k) {
            const float4 a0 = *(const float4*)(&As[k][ty * 8]);
            const float4 a1 = *(const float4*)(&As[k][ty * 8 + 4]);
            const float4 b  = *(const float4*)(&Bs[k][tx * 4]);
            const float avv[8] = {a0.x, a0.y, a0.z, a0.w, a1.x, a1.y, a1.z, a1.w};
            const float bvv[4] = {b.x, b.y, b.z, b.w};
            #pragma unroll
            for (int i = 0; i < 8; i++)
                #pragma unroll
                for (int j = 0; j < 4; j++)
                    acc[i][j] += avv[i] * bvv[j];
        }
    }

    float bsv[4];
    #pragma unroll
    for (int j = 0; j < 4; j++) {
        bsv[j] = bias1 ? bias1[n0 + tx * 4 + j] : 0.f;
        if (bias2) bsv[j] += bias2[n0 + tx * 4 + j];
    }
    #pragma unroll
    for (int i = 0; i < 8; i++) {
        const int m = m0 + ty * 8 + i;
        float4 o;
        o.x = acc[i][0] + bsv[0];
        o.y = acc[i][1] + bsv[1];
        o.z = acc[i][2] + bsv[2];
        o.w = acc[i][3] + bsv[3];
        *(float4*)(C + m * N + n0 + tx * 4) = o;
    }
}

// ---- small GEMM (64x64 tile) for the final projection (M=64) ----------------
#define BM 64
#define BN 64
#define BK 16

__global__ void __launch_bounds__(256)
gemm_nt_bias(const float* __restrict__ A, const float* __restrict__ B,
             const float* __restrict__ bias1, const float* __restrict__ bias2,
             float* __restrict__ C, int M, int N, int K)
{
    __shared__ __align__(16) float As[BK][BM];
    __shared__ __align__(16) float Bs[BK][BN];

    const int tid = threadIdx.x;
    const int m0 = blockIdx.x * BM;
    const int n0 = blockIdx.y * BN;
    const int tx = tid & 15;
    const int ty = tid >> 4;
    const int lr = tid >> 2;
    const int lc = tid & 3;

    float acc[4][4];
    #pragma unroll
    for (int i = 0; i < 4; i++)
        #pragma unroll
        for (int j = 0; j < 4; j++) acc[i][j] = 0.f;

    for (int kk0 = 0; kk0 < K; kk0 += BK) {
        const float4 av = *(const float4*)(A + (m0 + lr) * K + kk0 + lc * 4);
        const float4 bv = *(const float4*)(B + (n0 + lr) * K + kk0 + lc * 4);
        __syncthreads();
        As[lc*4+0][lr] = av.x; As[lc*4+1][lr] = av.y;
        As[lc*4+2][lr] = av.z; As[lc*4+3][lr] = av.w;
        Bs[lc*4+0][lr] = bv.x; Bs[lc*4+1][lr] = bv.y;
        Bs[lc*4+2][lr] = bv.z; Bs[lc*4+3][lr] = bv.w;
        __syncthreads();

        #pragma unroll
        for (int k = 0; k < BK; ++k) {
            const float4 a = *(const float4*)(&As[k][ty * 4]);
            const float4 b = *(const float4*)(&Bs[k][tx * 4]);
            const float avv[4] = {a.x, a.y, a.z, a.w};
            const float bvv[4] = {b.x, b.y, b.z, b.w};
            #pragma unroll
            for (int i = 0; i < 4; i++)
                #pragma unroll
                for (int j = 0; j < 4; j++)
                    acc[i][j] += avv[i] * bvv[j];
        }
    }

    #pragma unroll
    for (int i = 0; i < 4; i++) {
        const int m = m0 + ty * 4 + i;
        const int n = n0 + tx * 4;
        float bsv[4];
        #pragma unroll
        for (int j = 0; j < 4; j++) {
            bsv[j] = bias1 ? bias1[n + j] : 0.f;
            if (bias2) bsv[j] += bias2[n + j];
        }
        float4 o;
        o.x = acc[i][0] + bsv[0];
        o.y = acc[i][1] + bsv[1];
        o.z = acc[i][2] + bsv[2];
        o.w = acc[i][3] + bsv[3];
        *(float4*)(C + m * N + n) = o;
    }
}

// ---- launch -----------------------------------------------------------------
extern "C" void kernel_launch(void* const* d_in, const int* in_sizes, int n_in,
                              void* d_out, int out_size)
{
    const float* x     = (const float*)d_in[0];
    const float* W_ih0 = (const float*)d_in[1];
    const float* W_hh0 = (const float*)d_in[2];
    const float* b_ih0 = (const float*)d_in[3];
    const float* b_hh0 = (const float*)d_in[4];
    const float* W_ih1 = (const float*)d_in[5];
    const float* W_hh1 = (const float*)d_in[6];
    const float* b_ih1 = (const float*)d_in[7];
    const float* b_hh1 = (const float*)d_in[8];
    const float* W_out = (const float*)d_in[9];
    const float* b_out = (const float*)d_in[10];
    float* out = (float*)d_out;

    float *xp, *out0, *hfin;
    cudaGetSymbolAddress((void**)&xp,   g_xp);
    cudaGetSymbolAddress((void**)&out0, g_out0);
    cudaGetSymbolAddress((void**)&hfin, g_hfin);

    const int M = NB * NT;  // 32768

    // xp0 = x @ W_ih0^T + b_ih0 + b_hh0
    {
        dim3 grid(M / GBM, NH / GBN);
        gemm128_nt_bias<<<grid, 256>>>(x, W_ih0, b_ih0, b_hh0, xp, M, NH, NIN);
    }
    // layer 0 recurrence (stores full sequence)
    rnn_kernel<<<NCTA, RTHREADS>>>(xp, W_hh0, out0, 1);

    // xp1 = out0 @ W_ih1^T + b_ih1 + b_hh1
    {
        dim3 grid(M / GBM, NH / GBN);
        gemm128_nt_bias<<<grid, 256>>>(out0, W_ih1, b_ih1, b_hh1, xp, M, NH, NH);
    }
    // layer 1 recurrence (final hidden -> g_hfin)
    rnn_kernel<<<NCTA, RTHREADS>>>(xp, W_hh1, nullptr, 0);

    // out = h_last @ W_out^T + b_out
    {
        dim3 grid(NB / BM, NOUT / BN);
        gemm_nt_bias<<<grid, 256>>>(hfin, W_out, b_out, nullptr, out, NB, NOUT, NH);
    }
}